// round 1
// baseline (speedup 1.0000x reference)
#include <cuda_runtime.h>
#include <cuda_bf16.h>
#include <cfloat>
#include <cstdint>

// Problem constants
#define BB 8
#define NN 4096
#define CC 64
#define SS 1024
#define KK 32
#define MM (BB*SS*KK)      // 262144
#define C1 67              // 3 + 64
#define H1 64
#define H2 64
#define H3 128
#define EPSBN 1e-5f

#define OUT_XYZ_OFF 0
#define OUT_FEAT_OFF (BB*SS*3)   // 24576

// ---------------- scratch (static device globals; no allocs allowed) ----------------
__device__ int   d_fps_idx[BB*SS];
__device__ float d_newxyz[BB*SS*3];
__device__ int   d_gidx[MM];
__device__ float d_featT[BB*NN*CC];          // [b][n][c]
__device__ float d_g [MM*C1];                 // grouped input  [M,67]
__device__ float d_y1[MM*H1];
__device__ float d_y2[MM*H2];
__device__ float d_y3[MM*H3];

__device__ float d_sum1[H1],  d_sq1[H1];
__device__ float d_sum2[H2],  d_sq2[H2];
__device__ float d_sum3[H3],  d_sq3[H3];
__device__ float d_scale1[H1], d_shift1[H1];
__device__ float d_scale2[H2], d_shift2[H2];
__device__ float d_scale3[H3], d_shift3[H3];

// exact (non-FMA) squared distance, left-to-right sum — mirrors plain IEEE
__device__ __forceinline__ float sqdist3(float dx, float dy, float dz) {
    return __fadd_rn(__fadd_rn(__fmul_rn(dx,dx), __fmul_rn(dy,dy)), __fmul_rn(dz,dz));
}

// ---------------- zero stats ----------------
__global__ void zero_stats_kernel() {
    int t = threadIdx.x;
    if (t < H1) { d_sum1[t]=0.f; d_sq1[t]=0.f; }
    if (t < H2) { d_sum2[t]=0.f; d_sq2[t]=0.f; }
    if (t < H3) { d_sum3[t]=0.f; d_sq3[t]=0.f; }
}

// ---------------- FPS: one block per batch, 1024 threads, 4 pts/thread ----------------
__global__ __launch_bounds__(1024) void fps_kernel(const float* __restrict__ xyz) {
    int b = blockIdx.x;
    const float* px = xyz + (size_t)b*NN*3;
    int t = threadIdx.x;
    int lane = t & 31, warp = t >> 5;

    float X[4], Y[4], Z[4], D[4];
#pragma unroll
    for (int j = 0; j < 4; j++) {
        int p = t*4 + j;
        X[j] = px[p*3+0]; Y[j] = px[p*3+1]; Z[j] = px[p*3+2];
        D[j] = 1e10f;
    }

    __shared__ float s_v[32];
    __shared__ int   s_i[32];
    __shared__ int   s_far;

    int far = 0;
    for (int it = 0; it < SS; ++it) {
        if (t == 0) d_fps_idx[b*SS + it] = far;
        float cx = px[far*3+0], cy = px[far*3+1], cz = px[far*3+2];

        float bv = -1.0f; int bi = 0;
#pragma unroll
        for (int j = 0; j < 4; j++) {
            float d = sqdist3(X[j]-cx, Y[j]-cy, Z[j]-cz);
            D[j] = fminf(D[j], d);
            if (D[j] > bv) { bv = D[j]; bi = t*4 + j; }   // strict > keeps lowest idx
        }
        // warp argmax, ties -> lower index
#pragma unroll
        for (int off = 16; off > 0; off >>= 1) {
            float ov = __shfl_down_sync(0xffffffffu, bv, off);
            int   oi = __shfl_down_sync(0xffffffffu, bi, off);
            if (ov > bv || (ov == bv && oi < bi)) { bv = ov; bi = oi; }
        }
        if (lane == 0) { s_v[warp] = bv; s_i[warp] = bi; }
        __syncthreads();
        if (warp == 0) {
            bv = s_v[lane]; bi = s_i[lane];
#pragma unroll
            for (int off = 16; off > 0; off >>= 1) {
                float ov = __shfl_down_sync(0xffffffffu, bv, off);
                int   oi = __shfl_down_sync(0xffffffffu, bi, off);
                if (ov > bv || (ov == bv && oi < bi)) { bv = ov; bi = oi; }
            }
            if (lane == 0) s_far = bi;
        }
        __syncthreads();
        far = s_far;
    }
}

// ---------------- gather new_xyz (also to out) ----------------
__global__ void newxyz_kernel(const float* __restrict__ xyz, float* __restrict__ out) {
    int i = blockIdx.x * blockDim.x + threadIdx.x;   // b*S+s
    if (i >= BB*SS) return;
    int b = i / SS;
    int idx = d_fps_idx[i];
#pragma unroll
    for (int c = 0; c < 3; c++) {
        float v = xyz[((size_t)b*NN + idx)*3 + c];
        d_newxyz[i*3 + c] = v;
        out[OUT_XYZ_OFF + i*3 + c] = v;
    }
}

// ---------------- transpose features [B,C,N] -> [B,N,C] ----------------
__global__ void transpose_kernel(const float* __restrict__ f) {
    __shared__ float tile[32][33];
    int b  = blockIdx.z;
    int c0 = blockIdx.y * 32;
    int n0 = blockIdx.x * 32;
    int tx = threadIdx.x, ty = threadIdx.y;
    tile[ty][tx] = f[(size_t)b*CC*NN + (size_t)(c0+ty)*NN + (n0+tx)];
    __syncthreads();
    d_featT[(size_t)b*NN*CC + (size_t)(n0+ty)*CC + (c0+tx)] = tile[tx][ty];
}

// ---------------- kNN: one block (128 thr) per query ----------------
__global__ __launch_bounds__(128) void knn_kernel(const float* __restrict__ xyz) {
    int q = blockIdx.x;                 // b*S+s
    int b = q / SS;
    const float* px = xyz + (size_t)b*NN*3;

    __shared__ float sd[NN];            // 16KB
    __shared__ float wv[4];
    __shared__ int   wi[4];
    __shared__ int   s_sel;

    float qx = d_newxyz[q*3+0], qy = d_newxyz[q*3+1], qz = d_newxyz[q*3+2];

    int t = threadIdx.x;
    for (int p = t; p < NN; p += 128)
        sd[p] = sqdist3(px[p*3+0]-qx, px[p*3+1]-qy, px[p*3+2]-qz);
    __syncthreads();

    int lane = t & 31, warp = t >> 5;
    for (int kk = 0; kk < KK; ++kk) {
        float bv = FLT_MAX; int bi = 0x7fffffff;
        for (int p = t; p < NN; p += 128) {
            float v = sd[p];
            if (v < bv || (v == bv && p < bi)) { bv = v; bi = p; }
        }
#pragma unroll
        for (int off = 16; off > 0; off >>= 1) {
            float ov = __shfl_down_sync(0xffffffffu, bv, off);
            int   oi = __shfl_down_sync(0xffffffffu, bi, off);
            if (ov < bv || (ov == bv && oi < bi)) { bv = ov; bi = oi; }
        }
        if (lane == 0) { wv[warp] = bv; wi[warp] = bi; }
        __syncthreads();
        if (t == 0) {
            float fv = wv[0]; int fi = wi[0];
#pragma unroll
            for (int w = 1; w < 4; w++)
                if (wv[w] < fv || (wv[w] == fv && wi[w] < fi)) { fv = wv[w]; fi = wi[w]; }
            d_gidx[q*KK + kk] = fi;
            sd[fi] = FLT_MAX;
            s_sel = fi;
        }
        __syncthreads();
        (void)s_sel;
    }
}

// ---------------- gather grouped input g[M,67]: warp per row ----------------
__global__ __launch_bounds__(256) void gather_kernel(const float* __restrict__ xyz) {
    int warp = threadIdx.x >> 5, lane = threadIdx.x & 31;
    int m = blockIdx.x * 8 + warp;      // row
    int b = m >> 15;                    // / (S*K)
    int s = (m >> 5) & (SS-1);
    int idx = d_gidx[m];
    float* gr = d_g + (size_t)m * C1;
    if (lane < 3)
        gr[lane] = xyz[((size_t)b*NN + idx)*3 + lane] - d_newxyz[(b*SS + s)*3 + lane];
    const float* fr = d_featT + ((size_t)b*NN + idx)*CC;
    gr[3 + lane]      = fr[lane];
    gr[3 + 32 + lane] = fr[32 + lane];
}

// ---------------- GEMM: Y[M,COUT] = act(A[M,CIN]) @ W[COUT,CIN]^T ----------------
// act = identity (NORM=0) or relu(a*scale[c]+shift[c]) (NORM=1)
template<int CIN, int COUT, int BM, int TY, int TX, int NORM>
__global__ __launch_bounds__(256) void gemm_kernel(
    const float* __restrict__ A, const float* __restrict__ W,
    float* __restrict__ Y, const float* __restrict__ scale, const float* __restrict__ shift)
{
    constexpr int CINP = CIN + 1;
    __shared__ float As[BM][CINP];
    __shared__ __align__(16) float Ws[CIN][COUT];

    int tid = threadIdx.x;
    int m0 = blockIdx.x * BM;

    // load W transposed into Ws[k][c]
    for (int i = tid; i < CIN*COUT; i += 256) {
        int k = i / COUT, c = i % COUT;
        Ws[k][c] = W[c*CIN + k];
    }
    // load + activate A tile
    for (int i = tid; i < BM*CIN; i += 256) {
        int r = i / CIN, c = i % CIN;
        float a = A[(size_t)(m0 + r)*CIN + c];
        if (NORM) a = fmaxf(fmaf(a, scale[c], shift[c]), 0.0f);
        As[r][c] = a;
    }
    __syncthreads();

    int tx = tid % TX, ty = tid / TX;
    int r0 = ty*4, c0 = tx*4;

    float acc[4][4];
#pragma unroll
    for (int i = 0; i < 4; i++)
#pragma unroll
        for (int j = 0; j < 4; j++) acc[i][j] = 0.0f;

    for (int k = 0; k < CIN; k++) {
        float4 w = *(const float4*)&Ws[k][c0];
        float a0 = As[r0+0][k], a1 = As[r0+1][k], a2 = As[r0+2][k], a3 = As[r0+3][k];
        acc[0][0] += a0*w.x; acc[0][1] += a0*w.y; acc[0][2] += a0*w.z; acc[0][3] += a0*w.w;
        acc[1][0] += a1*w.x; acc[1][1] += a1*w.y; acc[1][2] += a1*w.z; acc[1][3] += a1*w.w;
        acc[2][0] += a2*w.x; acc[2][1] += a2*w.y; acc[2][2] += a2*w.z; acc[2][3] += a2*w.w;
        acc[3][0] += a3*w.x; acc[3][1] += a3*w.y; acc[3][2] += a3*w.z; acc[3][3] += a3*w.w;
    }
#pragma unroll
    for (int i = 0; i < 4; i++) {
        float4 v = make_float4(acc[i][0], acc[i][1], acc[i][2], acc[i][3]);
        *(float4*)&Y[(size_t)(m0 + r0 + i)*COUT + c0] = v;
    }
}

// ---------------- per-channel sum/sumsq over Y[M,Cn] ----------------
template<int Cn>
__global__ __launch_bounds__(256) void stats_kernel(const float* __restrict__ Y,
                                                    float* __restrict__ sum, float* __restrict__ sq)
{
    constexpr int TPR = 256 / Cn;           // rows processed per step
    int c  = threadIdx.x % Cn;
    int rr = threadIdx.x / Cn;
    int m0 = blockIdx.x * 1024;
    float s = 0.f, s2 = 0.f;
    for (int r = rr; r < 1024; r += TPR) {
        float v = Y[(size_t)(m0 + r)*Cn + c];
        s += v; s2 += v*v;
    }
    __shared__ float sh[256], sh2[256];
    sh[threadIdx.x] = s; sh2[threadIdx.x] = s2;
    __syncthreads();
    if (rr == 0) {
#pragma unroll
        for (int t = 1; t < TPR; t++) { s += sh[t*Cn + c]; s2 += sh2[t*Cn + c]; }
        atomicAdd(&sum[c], s);
        atomicAdd(&sq[c],  s2);
    }
}

// ---------------- fold BN stats into scale/shift ----------------
__global__ void finalize_kernel(int Cn, const float* __restrict__ sum, const float* __restrict__ sq,
                                const float* __restrict__ gamma, const float* __restrict__ beta,
                                float* __restrict__ scale, float* __restrict__ shift)
{
    int c = threadIdx.x;
    if (c < Cn) {
        const float invM = 1.0f / (float)MM;
        float mean = sum[c] * invM;
        float var  = sq[c] * invM - mean*mean;
        float iv   = rsqrtf(var + EPSBN);
        float sc   = iv * gamma[c];
        scale[c] = sc;
        shift[c] = beta[c] - mean*sc;
    }
}

// ---------------- BN3 + ReLU + max over K -> out [B,128,S] ----------------
__global__ __launch_bounds__(128) void maxout_kernel(float* __restrict__ out) {
    int q = blockIdx.x;            // b*S+s
    int b = q / SS, s = q % SS;
    int c = threadIdx.x;           // 0..127
    float sc = d_scale3[c], sh = d_shift3[c];
    const float* base = d_y3 + (size_t)q*KK*H3;
    float m = -FLT_MAX;
#pragma unroll 4
    for (int k = 0; k < KK; k++) {
        float v = fmaxf(fmaf(base[k*H3 + c], sc, sh), 0.0f);
        m = fmaxf(m, v);
    }
    out[OUT_FEAT_OFF + ((size_t)b*H3 + c)*SS + s] = m;
}

// ---------------- launch ----------------
extern "C" void kernel_launch(void* const* d_in, const int* in_sizes, int n_in,
                              void* d_out, int out_size)
{
    const float* xyz  = (const float*)d_in[0];
    const float* feat = (const float*)d_in[1];
    const float* W1 = (const float*)d_in[2];
    const float* g1 = (const float*)d_in[3];
    const float* b1 = (const float*)d_in[4];
    const float* W2 = (const float*)d_in[5];
    const float* g2 = (const float*)d_in[6];
    const float* b2 = (const float*)d_in[7];
    const float* W3 = (const float*)d_in[8];
    const float* g3 = (const float*)d_in[9];
    const float* b3 = (const float*)d_in[10];
    float* out = (float*)d_out;

    float *p_y1, *p_y2, *p_y3, *p_g;
    float *p_s1, *p_q1, *p_s2, *p_q2, *p_s3, *p_q3;
    float *p_sc1, *p_sh1, *p_sc2, *p_sh2, *p_sc3, *p_sh3;
    cudaGetSymbolAddress((void**)&p_g,  d_g);
    cudaGetSymbolAddress((void**)&p_y1, d_y1);
    cudaGetSymbolAddress((void**)&p_y2, d_y2);
    cudaGetSymbolAddress((void**)&p_y3, d_y3);
    cudaGetSymbolAddress((void**)&p_s1, d_sum1); cudaGetSymbolAddress((void**)&p_q1, d_sq1);
    cudaGetSymbolAddress((void**)&p_s2, d_sum2); cudaGetSymbolAddress((void**)&p_q2, d_sq2);
    cudaGetSymbolAddress((void**)&p_s3, d_sum3); cudaGetSymbolAddress((void**)&p_q3, d_sq3);
    cudaGetSymbolAddress((void**)&p_sc1, d_scale1); cudaGetSymbolAddress((void**)&p_sh1, d_shift1);
    cudaGetSymbolAddress((void**)&p_sc2, d_scale2); cudaGetSymbolAddress((void**)&p_sh2, d_shift2);
    cudaGetSymbolAddress((void**)&p_sc3, d_scale3); cudaGetSymbolAddress((void**)&p_sh3, d_shift3);

    zero_stats_kernel<<<1, 128>>>();
    fps_kernel<<<BB, 1024>>>(xyz);
    newxyz_kernel<<<(BB*SS + 255)/256, 256>>>(xyz, out);

    dim3 tgrid(NN/32, CC/32, BB);
    transpose_kernel<<<tgrid, dim3(32,32)>>>(feat);

    knn_kernel<<<BB*SS, 128>>>(xyz);
    gather_kernel<<<MM/8, 256>>>(xyz);

    // layer 1: [M,67] @ [64,67]^T
    gemm_kernel<C1, H1, 64, 16, 16, 0><<<MM/64, 256>>>(p_g, W1, p_y1, nullptr, nullptr);
    stats_kernel<H1><<<MM/1024, 256>>>(p_y1, p_s1, p_q1);
    finalize_kernel<<<1, 128>>>(H1, p_s1, p_q1, g1, b1, p_sc1, p_sh1);

    // layer 2: relu(bn(y1)) @ [64,64]^T
    gemm_kernel<H1, H2, 64, 16, 16, 1><<<MM/64, 256>>>(p_y1, W2, p_y2, p_sc1, p_sh1);
    stats_kernel<H2><<<MM/1024, 256>>>(p_y2, p_s2, p_q2);
    finalize_kernel<<<1, 128>>>(H2, p_s2, p_q2, g2, b2, p_sc2, p_sh2);

    // layer 3: relu(bn(y2)) @ [128,64]^T
    gemm_kernel<H2, H3, 32, 8, 32, 1><<<MM/32, 256>>>(p_y2, W3, p_y3, p_sc2, p_sh2);
    stats_kernel<H3><<<MM/1024, 256>>>(p_y3, p_s3, p_q3);
    finalize_kernel<<<1, 128>>>(H3, p_s3, p_q3, g3, b3, p_sc3, p_sh3);

    maxout_kernel<<<BB*SS, 128>>>(out);
}

// round 2
// speedup vs baseline: 1.3527x; 1.3527x over previous
#include <cuda_runtime.h>
#include <cuda_bf16.h>
#include <cfloat>
#include <cstdint>

// Problem constants
#define BB 8
#define NN 4096
#define CC 64
#define SS 1024
#define KK 32
#define MM (BB*SS*KK)      // 262144
#define H1 64
#define H2 64
#define H3 128
#define EPSBN 1e-5f

#define OUT_XYZ_OFF 0
#define OUT_FEAT_OFF (BB*SS*3)   // 24576

// ---------------- scratch ----------------
__device__ int   d_fps_idx[BB*SS];
__device__ float d_newxyz[BB*SS*3];
__device__ int   d_gidx[MM];
__device__ float d_featT[BB*NN*CC];          // [b][n][c]
__device__ float d_y1[MM*H1];
__device__ float d_y2[MM*H2];
__device__ float d_y3[MM*H3];

__device__ float d_sum1[H1],  d_sq1[H1];
__device__ float d_sum2[H2],  d_sq2[H2];
__device__ float d_sum3[H3],  d_sq3[H3];
__device__ float d_scale1[H1], d_shift1[H1];
__device__ float d_scale2[H2], d_shift2[H2];
__device__ float d_scale3[H3], d_shift3[H3];

// exact (non-FMA) squared distance, left-to-right sum
__device__ __forceinline__ float sqdist3(float dx, float dy, float dz) {
    return __fadd_rn(__fadd_rn(__fmul_rn(dx,dx), __fmul_rn(dy,dy)), __fmul_rn(dz,dz));
}

// ---------------- zero stats ----------------
__global__ void zero_stats_kernel() {
    int t = threadIdx.x;
    if (t < H1) { d_sum1[t]=0.f; d_sq1[t]=0.f; }
    if (t < H2) { d_sum2[t]=0.f; d_sq2[t]=0.f; }
    if (t < H3) { d_sum3[t]=0.f; d_sq3[t]=0.f; }
}

// ---------------- FPS: one block per batch, 512 threads, 8 pts/thread ----------------
__global__ __launch_bounds__(512) void fps_kernel(const float* __restrict__ xyz) {
    int b = blockIdx.x;
    const float* px = xyz + (size_t)b*NN*3;
    int t = threadIdx.x;
    int lane = t & 31, warp = t >> 5;     // 16 warps

    float X[8], Y[8], Z[8], D[8];
#pragma unroll
    for (int j = 0; j < 8; j++) {
        int p = j*512 + t;
        X[j] = px[p*3+0]; Y[j] = px[p*3+1]; Z[j] = px[p*3+2];
        D[j] = 1e10f;
    }

    __shared__ float s_v[16];
    __shared__ int   s_i[16];
    __shared__ int   s_far;

    int far = 0;
    for (int it = 0; it < SS; ++it) {
        if (t == 0) d_fps_idx[b*SS + it] = far;
        float cx = px[far*3+0], cy = px[far*3+1], cz = px[far*3+2];

        float bv = -1.0f; int bi = 0x7fffffff;
#pragma unroll
        for (int j = 0; j < 8; j++) {
            float d = sqdist3(X[j]-cx, Y[j]-cy, Z[j]-cz);
            D[j] = fminf(D[j], d);
            if (D[j] > bv) { bv = D[j]; bi = j*512 + t; }   // ascending index order
        }
#pragma unroll
        for (int off = 16; off > 0; off >>= 1) {
            float ov = __shfl_down_sync(0xffffffffu, bv, off);
            int   oi = __shfl_down_sync(0xffffffffu, bi, off);
            if (ov > bv || (ov == bv && oi < bi)) { bv = ov; bi = oi; }
        }
        if (lane == 0) { s_v[warp] = bv; s_i[warp] = bi; }
        __syncthreads();
        if (warp == 0) {
            bv = (lane < 16) ? s_v[lane] : -1.0f;
            bi = (lane < 16) ? s_i[lane] : 0x7fffffff;
#pragma unroll
            for (int off = 8; off > 0; off >>= 1) {
                float ov = __shfl_down_sync(0xffffffffu, bv, off);
                int   oi = __shfl_down_sync(0xffffffffu, bi, off);
                if (ov > bv || (ov == bv && oi < bi)) { bv = ov; bi = oi; }
            }
            if (lane == 0) s_far = bi;
        }
        __syncthreads();
        far = s_far;
    }
}

// ---------------- gather new_xyz (also to out) ----------------
__global__ void newxyz_kernel(const float* __restrict__ xyz, float* __restrict__ out) {
    int i = blockIdx.x * blockDim.x + threadIdx.x;   // b*S+s
    if (i >= BB*SS) return;
    int b = i / SS;
    int idx = d_fps_idx[i];
#pragma unroll
    for (int c = 0; c < 3; c++) {
        float v = xyz[((size_t)b*NN + idx)*3 + c];
        d_newxyz[i*3 + c] = v;
        out[OUT_XYZ_OFF + i*3 + c] = v;
    }
}

// ---------------- transpose features [B,C,N] -> [B,N,C] ----------------
__global__ void transpose_kernel(const float* __restrict__ f) {
    __shared__ float tile[32][33];
    int b  = blockIdx.z;
    int c0 = blockIdx.y * 32;
    int n0 = blockIdx.x * 32;
    int tx = threadIdx.x, ty = threadIdx.y;
    tile[ty][tx] = f[(size_t)b*CC*NN + (size_t)(c0+ty)*NN + (n0+tx)];
    __syncthreads();
    d_featT[(size_t)b*NN*CC + (size_t)(n0+ty)*CC + (c0+tx)] = tile[tx][ty];
}

// ---------------- kNN: register-resident selection, 128 thr/query ----------------
__global__ __launch_bounds__(128) void knn_kernel(const float* __restrict__ xyz) {
    int q = blockIdx.x;                 // b*S+s
    int b = q / SS;
    const float* px = xyz + (size_t)b*NN*3;
    int t = threadIdx.x;
    int lane = t & 31, warp = t >> 5;

    float qx = d_newxyz[q*3+0], qy = d_newxyz[q*3+1], qz = d_newxyz[q*3+2];

    float D[32];
#pragma unroll
    for (int i = 0; i < 32; i++) {
        int p = i*128 + t;
        D[i] = sqdist3(px[p*3+0]-qx, px[p*3+1]-qy, px[p*3+2]-qz);
    }
    // local argmin (ascending slot -> ascending global index; strict < keeps lowest)
    float bv = FLT_MAX; int bs = 0;
#pragma unroll
    for (int i = 0; i < 32; i++)
        if (D[i] < bv) { bv = D[i]; bs = i; }

    __shared__ float wv[4];
    __shared__ int   wi[4];

    for (int kk = 0; kk < KK; ++kk) {
        float v = bv; int p = bs*128 + t;
#pragma unroll
        for (int off = 16; off > 0; off >>= 1) {
            float ov = __shfl_down_sync(0xffffffffu, v, off);
            int   op = __shfl_down_sync(0xffffffffu, p, off);
            if (ov < v || (ov == v && op < p)) { v = ov; p = op; }
        }
        if (lane == 0) { wv[warp] = v; wi[warp] = p; }
        __syncthreads();
        float fv = wv[0]; int fp = wi[0];
#pragma unroll
        for (int w = 1; w < 4; w++)
            if (wv[w] < fv || (wv[w] == fv && wi[w] < fp)) { fv = wv[w]; fp = wi[w]; }
        if (t == 0) d_gidx[q*KK + kk] = fp;
        if ((fp & 127) == t) {
            D[fp >> 7] = FLT_MAX;
            float nv = FLT_MAX; int ns = 0;
#pragma unroll
            for (int i = 0; i < 32; i++)
                if (D[i] < nv) { nv = D[i]; ns = i; }
            bv = nv; bs = ns;
        }
        __syncthreads();
    }
}

// ---------------- fused MLP GEMM ----------------
// Y[m, cofs..cofs+63] = act(A[m, 0..CINK)) @ Wsub^T  , 64 output cols per launch.
// GATHER: build A tile on the fly from (xyz, featT, gidx); col layout [dx,dy,dz,0,f0..f63]
// NORM:   a -> relu(a*scale[c] + shift[c])
template<int CINK, bool GATHER, bool NORM>
__global__ __launch_bounds__(256) void mlp_gemm(
    const float* __restrict__ A, const float* __restrict__ W,
    float* __restrict__ Y, int ldY, int cofs,
    const float* __restrict__ scale, const float* __restrict__ shift,
    const float* __restrict__ xyz)
{
    constexpr int BM = 64;
    constexpr int ASTR = 69;            // odd stride -> conflict-free MMA loads
    constexpr int WSTR = 68;            // 16B-aligned float4 rows
    __shared__ float As[BM*ASTR];
    __shared__ float Ws[CINK*WSTR];

    int tid = threadIdx.x;
    int m0 = blockIdx.x * BM;

    // ---- W load (coalesced along k) ----
    if (GATHER) {
        for (int i = tid; i < CINK*64; i += 256) {
            int k = i % CINK;        // CINK = 68
            int c = i / CINK;
            float v = 0.0f;
            if (k != 3) v = W[c*67 + (k < 3 ? k : k-1)];
            Ws[k*WSTR + c] = v;
        }
    } else {
        for (int i = tid; i < CINK*64; i += 256) {
            int k = i % CINK;
            int c = i / CINK;
            Ws[k*WSTR + c] = W[c*CINK + k];
        }
    }

    // ---- A tile ----
    if (GATHER) {
        int warp = tid >> 5, lane = tid & 31;
        for (int r = warp; r < BM; r += 8) {
            int m = m0 + r;
            int b = m >> 15;
            int s = (m >> 5) & (SS-1);
            int idx = d_gidx[m];
            if (lane < 16) {
                const float4* f4 = (const float4*)(d_featT + ((size_t)(b*NN + idx))*CC);
                float4 v = f4[lane];
                float* dst = &As[r*ASTR + 4 + lane*4];
                dst[0] = v.x; dst[1] = v.y; dst[2] = v.z; dst[3] = v.w;
            } else if (lane < 19) {
                int c = lane - 16;
                As[r*ASTR + c] = xyz[((size_t)(b*NN + idx))*3 + c]
                               - d_newxyz[(b*SS + s)*3 + c];
            } else if (lane == 19) {
                As[r*ASTR + 3] = 0.0f;
            }
        }
    } else {
        const float4* A4 = (const float4*)(A + (size_t)m0*CINK);
        for (int i = tid; i < BM*(CINK/4); i += 256) {
            int r  = i >> 4;       // CINK/4 == 16
            int cg = i & 15;
            float4 v = A4[i];
            if (NORM) {
                int c = cg*4;
                v.x = fmaxf(fmaf(v.x, __ldg(&scale[c+0]), __ldg(&shift[c+0])), 0.0f);
                v.y = fmaxf(fmaf(v.y, __ldg(&scale[c+1]), __ldg(&shift[c+1])), 0.0f);
                v.z = fmaxf(fmaf(v.z, __ldg(&scale[c+2]), __ldg(&shift[c+2])), 0.0f);
                v.w = fmaxf(fmaf(v.w, __ldg(&scale[c+3]), __ldg(&shift[c+3])), 0.0f);
            }
            float* dst = &As[r*ASTR + cg*4];
            dst[0] = v.x; dst[1] = v.y; dst[2] = v.z; dst[3] = v.w;
        }
    }
    __syncthreads();

    // ---- MMA: 4 rows x 4 cols per thread ----
    int tx = tid & 15, ty = tid >> 4;
    int r0 = ty*4, c0 = tx*4;
    float acc[4][4];
#pragma unroll
    for (int i = 0; i < 4; i++)
#pragma unroll
        for (int j = 0; j < 4; j++) acc[i][j] = 0.0f;

#pragma unroll 8
    for (int k = 0; k < CINK; k++) {
        float4 w = *(const float4*)&Ws[k*WSTR + c0];
        float a0 = As[(r0+0)*ASTR + k];
        float a1 = As[(r0+1)*ASTR + k];
        float a2 = As[(r0+2)*ASTR + k];
        float a3 = As[(r0+3)*ASTR + k];
        acc[0][0]=fmaf(a0,w.x,acc[0][0]); acc[0][1]=fmaf(a0,w.y,acc[0][1]); acc[0][2]=fmaf(a0,w.z,acc[0][2]); acc[0][3]=fmaf(a0,w.w,acc[0][3]);
        acc[1][0]=fmaf(a1,w.x,acc[1][0]); acc[1][1]=fmaf(a1,w.y,acc[1][1]); acc[1][2]=fmaf(a1,w.z,acc[1][2]); acc[1][3]=fmaf(a1,w.w,acc[1][3]);
        acc[2][0]=fmaf(a2,w.x,acc[2][0]); acc[2][1]=fmaf(a2,w.y,acc[2][1]); acc[2][2]=fmaf(a2,w.z,acc[2][2]); acc[2][3]=fmaf(a2,w.w,acc[2][3]);
        acc[3][0]=fmaf(a3,w.x,acc[3][0]); acc[3][1]=fmaf(a3,w.y,acc[3][1]); acc[3][2]=fmaf(a3,w.z,acc[3][2]); acc[3][3]=fmaf(a3,w.w,acc[3][3]);
    }

#pragma unroll
    for (int i = 0; i < 4; i++) {
        float4 v = make_float4(acc[i][0], acc[i][1], acc[i][2], acc[i][3]);
        *(float4*)&Y[(size_t)(m0 + r0 + i)*ldY + cofs + c0] = v;
    }
}

// ---------------- per-channel sum/sumsq over Y[M,Cn] ----------------
template<int Cn>
__global__ __launch_bounds__(256) void stats_kernel(const float* __restrict__ Y,
                                                    float* __restrict__ sum, float* __restrict__ sq)
{
    constexpr int TPR = 256 / Cn;
    int c  = threadIdx.x % Cn;
    int rr = threadIdx.x / Cn;
    int m0 = blockIdx.x * 1024;
    float s = 0.f, s2 = 0.f;
    for (int r = rr; r < 1024; r += TPR) {
        float v = Y[(size_t)(m0 + r)*Cn + c];
        s += v; s2 += v*v;
    }
    __shared__ float sh[256], sh2[256];
    sh[threadIdx.x] = s; sh2[threadIdx.x] = s2;
    __syncthreads();
    if (rr == 0) {
#pragma unroll
        for (int t = 1; t < TPR; t++) { s += sh[t*Cn + c]; s2 += sh2[t*Cn + c]; }
        atomicAdd(&sum[c], s);
        atomicAdd(&sq[c],  s2);
    }
}

// ---------------- fold BN stats into scale/shift ----------------
__global__ void finalize_kernel(int Cn, const float* __restrict__ sum, const float* __restrict__ sq,
                                const float* __restrict__ gamma, const float* __restrict__ beta,
                                float* __restrict__ scale, float* __restrict__ shift)
{
    int c = threadIdx.x;
    if (c < Cn) {
        const float invM = 1.0f / (float)MM;
        float mean = sum[c] * invM;
        float var  = sq[c] * invM - mean*mean;
        float iv   = rsqrtf(var + EPSBN);
        float sc   = iv * gamma[c];
        scale[c] = sc;
        shift[c] = beta[c] - mean*sc;
    }
}

// ---------------- BN3 + ReLU + max over K -> out [B,128,S] ----------------
__global__ __launch_bounds__(128) void maxout_kernel(float* __restrict__ out) {
    int q = blockIdx.x;            // b*S+s
    int b = q / SS, s = q % SS;
    int c = threadIdx.x;           // 0..127
    float sc = d_scale3[c], sh = d_shift3[c];
    const float* base = d_y3 + (size_t)q*KK*H3;
    float m = -FLT_MAX;
#pragma unroll 4
    for (int k = 0; k < KK; k++) {
        float v = fmaxf(fmaf(base[k*H3 + c], sc, sh), 0.0f);
        m = fmaxf(m, v);
    }
    out[OUT_FEAT_OFF + ((size_t)b*H3 + c)*SS + s] = m;
}

// ---------------- launch ----------------
extern "C" void kernel_launch(void* const* d_in, const int* in_sizes, int n_in,
                              void* d_out, int out_size)
{
    const float* xyz  = (const float*)d_in[0];
    const float* feat = (const float*)d_in[1];
    const float* W1 = (const float*)d_in[2];
    const float* g1 = (const float*)d_in[3];
    const float* b1 = (const float*)d_in[4];
    const float* W2 = (const float*)d_in[5];
    const float* g2 = (const float*)d_in[6];
    const float* b2 = (const float*)d_in[7];
    const float* W3 = (const float*)d_in[8];
    const float* g3 = (const float*)d_in[9];
    const float* b3 = (const float*)d_in[10];
    float* out = (float*)d_out;

    float *p_y1, *p_y2, *p_y3;
    float *p_s1, *p_q1, *p_s2, *p_q2, *p_s3, *p_q3;
    float *p_sc1, *p_sh1, *p_sc2, *p_sh2, *p_sc3, *p_sh3;
    cudaGetSymbolAddress((void**)&p_y1, d_y1);
    cudaGetSymbolAddress((void**)&p_y2, d_y2);
    cudaGetSymbolAddress((void**)&p_y3, d_y3);
    cudaGetSymbolAddress((void**)&p_s1, d_sum1); cudaGetSymbolAddress((void**)&p_q1, d_sq1);
    cudaGetSymbolAddress((void**)&p_s2, d_sum2); cudaGetSymbolAddress((void**)&p_q2, d_sq2);
    cudaGetSymbolAddress((void**)&p_s3, d_sum3); cudaGetSymbolAddress((void**)&p_q3, d_sq3);
    cudaGetSymbolAddress((void**)&p_sc1, d_scale1); cudaGetSymbolAddress((void**)&p_sh1, d_shift1);
    cudaGetSymbolAddress((void**)&p_sc2, d_scale2); cudaGetSymbolAddress((void**)&p_sh2, d_shift2);
    cudaGetSymbolAddress((void**)&p_sc3, d_scale3); cudaGetSymbolAddress((void**)&p_sh3, d_shift3);

    zero_stats_kernel<<<1, 128>>>();
    fps_kernel<<<BB, 512>>>(xyz);
    newxyz_kernel<<<(BB*SS + 255)/256, 256>>>(xyz, out);

    dim3 tgrid(NN/32, CC/32, BB);
    transpose_kernel<<<tgrid, dim3(32,32)>>>(feat);

    knn_kernel<<<BB*SS, 128>>>(xyz);

    // layer 1 (gather fused): [M,68p] @ W1^T -> y1 [M,64]
    mlp_gemm<68, true, false><<<MM/64, 256>>>(nullptr, W1, p_y1, H1, 0, nullptr, nullptr, xyz);
    stats_kernel<H1><<<MM/1024, 256>>>(p_y1, p_s1, p_q1);
    finalize_kernel<<<1, 128>>>(H1, p_s1, p_q1, g1, b1, p_sc1, p_sh1);

    // layer 2: relu(bn(y1)) @ W2^T -> y2 [M,64]
    mlp_gemm<64, false, true><<<MM/64, 256>>>(p_y1, W2, p_y2, H2, 0, p_sc1, p_sh1, nullptr);
    stats_kernel<H2><<<MM/1024, 256>>>(p_y2, p_s2, p_q2);
    finalize_kernel<<<1, 128>>>(H2, p_s2, p_q2, g2, b2, p_sc2, p_sh2);

    // layer 3 (two column halves): relu(bn(y2)) @ W3^T -> y3 [M,128]
    mlp_gemm<64, false, true><<<MM/64, 256>>>(p_y2, W3,        p_y3, H3, 0,  p_sc2, p_sh2, nullptr);
    mlp_gemm<64, false, true><<<MM/64, 256>>>(p_y2, W3 + 64*64, p_y3, H3, 64, p_sc2, p_sh2, nullptr);
    stats_kernel<H3><<<MM/1024, 256>>>(p_y3, p_s3, p_q3);
    finalize_kernel<<<1, 128>>>(H3, p_s3, p_q3, g3, b3, p_sc3, p_sh3);

    maxout_kernel<<<BB*SS, 128>>>(out);
}

// round 3
// speedup vs baseline: 2.0205x; 1.4937x over previous
#include <cuda_runtime.h>
#include <cuda_bf16.h>
#include <cfloat>
#include <cstdint>

// Problem constants
#define BB 8
#define NN 4096
#define CC 64
#define SS 1024
#define KK 32
#define MM (BB*SS*KK)      // 262144
#define H1 64
#define H2 64
#define H3 128
#define EPSBN 1e-5f

#define OUT_XYZ_OFF 0
#define OUT_FEAT_OFF (BB*SS*3)   // 24576

// ---------------- scratch ----------------
__device__ int   d_fps_idx[BB*SS];
__device__ float d_newxyz[BB*SS*3];
__device__ int   d_gidx[MM];
__device__ float d_featT[BB*NN*CC];          // [b][n][c]
__device__ float d_y1[MM*H1];
__device__ float d_y2[MM*H2];
__device__ float d_qmax[BB*SS*H3];
__device__ float d_qmin[BB*SS*H3];

__device__ float d_sum1[H1],  d_sq1[H1];
__device__ float d_sum2[H2],  d_sq2[H2];
__device__ float d_sum3[H3],  d_sq3[H3];
__device__ float d_scale1[H1], d_shift1[H1];
__device__ float d_scale2[H2], d_shift2[H2];
__device__ float d_scale3[H3], d_shift3[H3];

// exact (non-FMA) squared distance, left-to-right sum
__device__ __forceinline__ float sqdist3(float dx, float dy, float dz) {
    return __fadd_rn(__fadd_rn(__fmul_rn(dx,dx), __fmul_rn(dy,dy)), __fmul_rn(dz,dz));
}

// ---------------- zero stats ----------------
__global__ void zero_stats_kernel() {
    int t = threadIdx.x;
    if (t < H1) { d_sum1[t]=0.f; d_sq1[t]=0.f; }
    if (t < H2) { d_sum2[t]=0.f; d_sq2[t]=0.f; }
    if (t < H3) { d_sum3[t]=0.f; d_sq3[t]=0.f; }
}

// ---------------- FPS: 1024 threads, 4 pts/thread, redux + single barrier ----------------
__global__ __launch_bounds__(1024) void fps_kernel(const float* __restrict__ xyz) {
    int b = blockIdx.x;
    const float* px = xyz + (size_t)b*NN*3;
    int t = threadIdx.x;
    int lane = t & 31, warp = t >> 5;     // 32 warps

    float X[4], Y[4], Z[4], D[4];
#pragma unroll
    for (int j = 0; j < 4; j++) {
        int p = j*1024 + t;
        X[j] = px[p*3+0]; Y[j] = px[p*3+1]; Z[j] = px[p*3+2];
        D[j] = 1e10f;
    }

    __shared__ unsigned s_v[2][32];
    __shared__ unsigned s_i[2][32];

    int far = 0;
    int par = 0;
    for (int it = 0; it < SS; ++it) {
        if (t == 0) d_fps_idx[b*SS + it] = far;
        float cx = px[far*3+0], cy = px[far*3+1], cz = px[far*3+2];

        float bv = -1.0f; int bi = 0;
#pragma unroll
        for (int j = 0; j < 4; j++) {
            float d = sqdist3(X[j]-cx, Y[j]-cy, Z[j]-cz);
            D[j] = fminf(D[j], d);
            if (D[j] > bv) { bv = D[j]; bi = j*1024 + t; }   // ascending index, strict >
        }
        // warp argmax via redux: max value bits (dist>=0 -> monotone), then min index among ties
        unsigned db   = __float_as_uint(bv);
        unsigned vmax = __reduce_max_sync(0xffffffffu, db);
        unsigned imin = __reduce_min_sync(0xffffffffu, (db == vmax) ? (unsigned)bi : 0xffffffffu);
        if (lane == 0) { s_v[par][warp] = vmax; s_i[par][warp] = imin; }
        __syncthreads();
        // every warp reduces the 32 partials itself (no 2nd barrier; parity double-buffer)
        unsigned v2 = s_v[par][lane];
        unsigned i2 = s_i[par][lane];
        unsigned vm2 = __reduce_max_sync(0xffffffffu, v2);
        unsigned im2 = __reduce_min_sync(0xffffffffu, (v2 == vm2) ? i2 : 0xffffffffu);
        far = (int)im2;
        par ^= 1;
    }
}

// ---------------- gather new_xyz (also to out) ----------------
__global__ void newxyz_kernel(const float* __restrict__ xyz, float* __restrict__ out) {
    int i = blockIdx.x * blockDim.x + threadIdx.x;   // b*S+s
    if (i >= BB*SS) return;
    int b = i / SS;
    int idx = d_fps_idx[i];
#pragma unroll
    for (int c = 0; c < 3; c++) {
        float v = xyz[((size_t)b*NN + idx)*3 + c];
        d_newxyz[i*3 + c] = v;
        out[OUT_XYZ_OFF + i*3 + c] = v;
    }
}

// ---------------- transpose features [B,C,N] -> [B,N,C] ----------------
__global__ void transpose_kernel(const float* __restrict__ f) {
    __shared__ float tile[32][33];
    int b  = blockIdx.z;
    int c0 = blockIdx.y * 32;
    int n0 = blockIdx.x * 32;
    int tx = threadIdx.x, ty = threadIdx.y;
    tile[ty][tx] = f[(size_t)b*CC*NN + (size_t)(c0+ty)*NN + (n0+tx)];
    __syncthreads();
    d_featT[(size_t)b*NN*CC + (size_t)(n0+ty)*CC + (c0+tx)] = tile[tx][ty];
}

// ---------------- kNN: register-resident, redux, single barrier/round ----------------
__global__ __launch_bounds__(128) void knn_kernel(const float* __restrict__ xyz) {
    int q = blockIdx.x;                 // b*S+s
    int b = q / SS;
    const float* px = xyz + (size_t)b*NN*3;
    int t = threadIdx.x;
    int lane = t & 31, warp = t >> 5;

    float qx = d_newxyz[q*3+0], qy = d_newxyz[q*3+1], qz = d_newxyz[q*3+2];

    float D[32];
#pragma unroll
    for (int i = 0; i < 32; i++) {
        int p = i*128 + t;
        D[i] = sqdist3(px[p*3+0]-qx, px[p*3+1]-qy, px[p*3+2]-qz);
    }
    float bv = FLT_MAX; int bs = 0;
#pragma unroll
    for (int i = 0; i < 32; i++)
        if (D[i] < bv) { bv = D[i]; bs = i; }   // lowest slot -> lowest global idx

    __shared__ unsigned wv[2][4];
    __shared__ unsigned wi[2][4];

    int par = 0;
    for (int kk = 0; kk < KK; ++kk) {
        unsigned db   = __float_as_uint(bv);
        unsigned vmin = __reduce_min_sync(0xffffffffu, db);
        unsigned p    = (unsigned)(bs*128 + t);
        unsigned imin = __reduce_min_sync(0xffffffffu, (db == vmin) ? p : 0xffffffffu);
        if (lane == 0) { wv[par][warp] = vmin; wi[par][warp] = imin; }
        __syncthreads();
        unsigned v2 = (lane < 4) ? wv[par][lane] : 0xffffffffu;
        unsigned i2 = (lane < 4) ? wi[par][lane] : 0xffffffffu;
        unsigned vb = __reduce_min_sync(0xffffffffu, v2);
        unsigned fb = __reduce_min_sync(0xffffffffu, (v2 == vb) ? i2 : 0xffffffffu);
        if (t == 0) d_gidx[q*KK + kk] = (int)fb;
        if ((fb & 127u) == (unsigned)t) {
            D[fb >> 7] = FLT_MAX;
            float nv = FLT_MAX; int ns = 0;
#pragma unroll
            for (int i = 0; i < 32; i++)
                if (D[i] < nv) { nv = D[i]; ns = i; }
            bv = nv; bs = ns;
        }
        par ^= 1;
    }
}

// ---------------- fused MLP GEMM (layers 1,2): Y[M,64], stats fused ----------------
template<int CINK, bool GATHER, bool NORM>
__global__ __launch_bounds__(256) void mlp_gemm(
    const float* __restrict__ A, const float* __restrict__ W,
    float* __restrict__ Y,
    const float* __restrict__ scale, const float* __restrict__ shift,
    const float* __restrict__ xyz,
    float* __restrict__ gsum, float* __restrict__ gsq)
{
    constexpr int BM = 64;
    constexpr int ASTR = 69;            // odd stride -> conflict-free MMA loads
    constexpr int WSTR = 68;            // 16B-aligned float4 rows
    __shared__ float As[BM*ASTR];
    __shared__ float Ws[CINK*WSTR];
    __shared__ float s_sum[64], s_sq[64];

    int tid = threadIdx.x;
    int m0 = blockIdx.x * BM;

    if (tid < 64) { s_sum[tid] = 0.f; s_sq[tid] = 0.f; }

    // ---- W load ----
    if (GATHER) {
        for (int i = tid; i < CINK*64; i += 256) {
            int k = i % CINK;        // CINK = 68, col 3 is zero pad
            int c = i / CINK;
            float v = 0.0f;
            if (k != 3) v = W[c*67 + (k < 3 ? k : k-1)];
            Ws[k*WSTR + c] = v;
        }
    } else {
        for (int i = tid; i < CINK*64; i += 256) {
            int k = i % CINK;
            int c = i / CINK;
            Ws[k*WSTR + c] = W[c*CINK + k];
        }
    }

    // ---- A tile ----
    if (GATHER) {
        int warp = tid >> 5, lane = tid & 31;
        for (int r = warp; r < BM; r += 8) {
            int m = m0 + r;
            int b = m >> 15;
            int s = (m >> 5) & (SS-1);
            int idx = d_gidx[m];
            if (lane < 16) {
                const float4* f4 = (const float4*)(d_featT + ((size_t)(b*NN + idx))*CC);
                float4 v = f4[lane];
                float* dst = &As[r*ASTR + 4 + lane*4];
                dst[0] = v.x; dst[1] = v.y; dst[2] = v.z; dst[3] = v.w;
            } else if (lane < 19) {
                int c = lane - 16;
                As[r*ASTR + c] = xyz[((size_t)(b*NN + idx))*3 + c]
                               - d_newxyz[(b*SS + s)*3 + c];
            } else if (lane == 19) {
                As[r*ASTR + 3] = 0.0f;
            }
        }
    } else {
        const float4* A4 = (const float4*)(A + (size_t)m0*CINK);
        for (int i = tid; i < BM*(CINK/4); i += 256) {
            int r  = i >> 4;       // CINK/4 == 16
            int cg = i & 15;
            float4 v = A4[i];
            if (NORM) {
                int c = cg*4;
                v.x = fmaxf(fmaf(v.x, __ldg(&scale[c+0]), __ldg(&shift[c+0])), 0.0f);
                v.y = fmaxf(fmaf(v.y, __ldg(&scale[c+1]), __ldg(&shift[c+1])), 0.0f);
                v.z = fmaxf(fmaf(v.z, __ldg(&scale[c+2]), __ldg(&shift[c+2])), 0.0f);
                v.w = fmaxf(fmaf(v.w, __ldg(&scale[c+3]), __ldg(&shift[c+3])), 0.0f);
            }
            float* dst = &As[r*ASTR + cg*4];
            dst[0] = v.x; dst[1] = v.y; dst[2] = v.z; dst[3] = v.w;
        }
    }
    __syncthreads();

    // ---- MMA: 4 rows x 4 cols per thread ----
    int tx = tid & 15, ty = tid >> 4;
    int r0 = ty*4, c0 = tx*4;
    float acc[4][4];
#pragma unroll
    for (int i = 0; i < 4; i++)
#pragma unroll
        for (int j = 0; j < 4; j++) acc[i][j] = 0.0f;

#pragma unroll 8
    for (int k = 0; k < CINK; k++) {
        float4 w = *(const float4*)&Ws[k*WSTR + c0];
        float a0 = As[(r0+0)*ASTR + k];
        float a1 = As[(r0+1)*ASTR + k];
        float a2 = As[(r0+2)*ASTR + k];
        float a3 = As[(r0+3)*ASTR + k];
        acc[0][0]=fmaf(a0,w.x,acc[0][0]); acc[0][1]=fmaf(a0,w.y,acc[0][1]); acc[0][2]=fmaf(a0,w.z,acc[0][2]); acc[0][3]=fmaf(a0,w.w,acc[0][3]);
        acc[1][0]=fmaf(a1,w.x,acc[1][0]); acc[1][1]=fmaf(a1,w.y,acc[1][1]); acc[1][2]=fmaf(a1,w.z,acc[1][2]); acc[1][3]=fmaf(a1,w.w,acc[1][3]);
        acc[2][0]=fmaf(a2,w.x,acc[2][0]); acc[2][1]=fmaf(a2,w.y,acc[2][1]); acc[2][2]=fmaf(a2,w.z,acc[2][2]); acc[2][3]=fmaf(a2,w.w,acc[2][3]);
        acc[3][0]=fmaf(a3,w.x,acc[3][0]); acc[3][1]=fmaf(a3,w.y,acc[3][1]); acc[3][2]=fmaf(a3,w.z,acc[3][2]); acc[3][3]=fmaf(a3,w.w,acc[3][3]);
    }

    // ---- fused stats partials ----
#pragma unroll
    for (int j = 0; j < 4; j++) {
        float ls = 0.f, lq = 0.f;
#pragma unroll
        for (int i = 0; i < 4; i++) { float v = acc[i][j]; ls += v; lq += v*v; }
        atomicAdd(&s_sum[c0+j], ls);
        atomicAdd(&s_sq [c0+j], lq);
    }
#pragma unroll
    for (int i = 0; i < 4; i++) {
        float4 v = make_float4(acc[i][0], acc[i][1], acc[i][2], acc[i][3]);
        *(float4*)&Y[(size_t)(m0 + r0 + i)*64 + c0] = v;
    }
    __syncthreads();
    if (tid < 64) {
        atomicAdd(&gsum[tid], s_sum[tid]);
        atomicAdd(&gsq [tid], s_sq [tid]);
    }
}

// ---------------- layer-3 GEMM: one query per block, no Y store ----------------
// outputs per-(q,c) max/min of raw accs + BN stats partials
__global__ __launch_bounds__(256) void gemm3_kernel(
    const float* __restrict__ A, const float* __restrict__ W,
    const float* __restrict__ scale, const float* __restrict__ shift)
{
    constexpr int BM = 32;              // = KK, one query per block
    constexpr int ASTR = 69;
    constexpr int WSTR = 132;
    __shared__ float As[BM*ASTR];           // 8832 B
    __shared__ float Ws[64*WSTR];           // 33792 B
    __shared__ float red[8][128];           // 4096 B
    __shared__ float s_sum[128], s_sq[128]; // 1024 B

    int tid = threadIdx.x;
    int q  = blockIdx.x;
    int m0 = q * BM;

    if (tid < 128) { s_sum[tid] = 0.f; s_sq[tid] = 0.f; }

    // W load: Ws[k][c] = W[c*64+k], c in [0,128)
    for (int i = tid; i < 64*128; i += 256) {
        int k = i & 63;
        int c = i >> 6;
        Ws[k*WSTR + c] = W[c*64 + k];
    }
    // A tile with BN+ReLU
    const float4* A4 = (const float4*)(A + (size_t)m0*64);
    for (int i = tid; i < BM*16; i += 256) {
        int r  = i >> 4;
        int cg = i & 15;
        float4 v = A4[i];
        int c = cg*4;
        v.x = fmaxf(fmaf(v.x, __ldg(&scale[c+0]), __ldg(&shift[c+0])), 0.0f);
        v.y = fmaxf(fmaf(v.y, __ldg(&scale[c+1]), __ldg(&shift[c+1])), 0.0f);
        v.z = fmaxf(fmaf(v.z, __ldg(&scale[c+2]), __ldg(&shift[c+2])), 0.0f);
        v.w = fmaxf(fmaf(v.w, __ldg(&scale[c+3]), __ldg(&shift[c+3])), 0.0f);
        float* dst = &As[r*ASTR + cg*4];
        dst[0] = v.x; dst[1] = v.y; dst[2] = v.z; dst[3] = v.w;
    }
    __syncthreads();

    // MMA: 32 tx x 8 ty; 4 rows x 4 cols per thread
    int tx = tid & 31, ty = tid >> 5;
    int r0 = ty*4, c0 = tx*4;
    float acc[4][4];
#pragma unroll
    for (int i = 0; i < 4; i++)
#pragma unroll
        for (int j = 0; j < 4; j++) acc[i][j] = 0.0f;

#pragma unroll 8
    for (int k = 0; k < 64; k++) {
        float4 w = *(const float4*)&Ws[k*WSTR + c0];
        float a0 = As[(r0+0)*ASTR + k];
        float a1 = As[(r0+1)*ASTR + k];
        float a2 = As[(r0+2)*ASTR + k];
        float a3 = As[(r0+3)*ASTR + k];
        acc[0][0]=fmaf(a0,w.x,acc[0][0]); acc[0][1]=fmaf(a0,w.y,acc[0][1]); acc[0][2]=fmaf(a0,w.z,acc[0][2]); acc[0][3]=fmaf(a0,w.w,acc[0][3]);
        acc[1][0]=fmaf(a1,w.x,acc[1][0]); acc[1][1]=fmaf(a1,w.y,acc[1][1]); acc[1][2]=fmaf(a1,w.z,acc[1][2]); acc[1][3]=fmaf(a1,w.w,acc[1][3]);
        acc[2][0]=fmaf(a2,w.x,acc[2][0]); acc[2][1]=fmaf(a2,w.y,acc[2][1]); acc[2][2]=fmaf(a2,w.z,acc[2][2]); acc[2][3]=fmaf(a2,w.w,acc[2][3]);
        acc[3][0]=fmaf(a3,w.x,acc[3][0]); acc[3][1]=fmaf(a3,w.y,acc[3][1]); acc[3][2]=fmaf(a3,w.z,acc[3][2]); acc[3][3]=fmaf(a3,w.w,acc[3][3]);
    }

    // per-thread partials
    float tmax[4], tmin[4];
#pragma unroll
    for (int j = 0; j < 4; j++) {
        float ls = 0.f, lq = 0.f;
        float mx = acc[0][j], mn = acc[0][j];
#pragma unroll
        for (int i = 0; i < 4; i++) {
            float v = acc[i][j];
            ls += v; lq += v*v;
            mx = fmaxf(mx, v); mn = fminf(mn, v);
        }
        atomicAdd(&s_sum[c0+j], ls);
        atomicAdd(&s_sq [c0+j], lq);
        tmax[j] = mx; tmin[j] = mn;
    }
    // reduce max over 8 ty groups
#pragma unroll
    for (int j = 0; j < 4; j++) red[ty][c0+j] = tmax[j];
    __syncthreads();
    if (tid < 128) {
        float m = red[0][tid];
#pragma unroll
        for (int w = 1; w < 8; w++) m = fmaxf(m, red[w][tid]);
        d_qmax[(size_t)q*128 + tid] = m;
    }
    __syncthreads();
#pragma unroll
    for (int j = 0; j < 4; j++) red[ty][c0+j] = tmin[j];
    __syncthreads();
    if (tid < 128) {
        float m = red[0][tid];
#pragma unroll
        for (int w = 1; w < 8; w++) m = fminf(m, red[w][tid]);
        d_qmin[(size_t)q*128 + tid] = m;
        atomicAdd(&d_sum3[tid], s_sum[tid]);
        atomicAdd(&d_sq3 [tid], s_sq [tid]);
    }
}

// ---------------- fold BN stats into scale/shift ----------------
__global__ void finalize_kernel(int Cn, const float* __restrict__ sum, const float* __restrict__ sq,
                                const float* __restrict__ gamma, const float* __restrict__ beta,
                                float* __restrict__ scale, float* __restrict__ shift)
{
    int c = threadIdx.x;
    if (c < Cn) {
        const float invM = 1.0f / (float)MM;
        float mean = sum[c] * invM;
        float var  = sq[c] * invM - mean*mean;
        float iv   = rsqrtf(var + EPSBN);
        float sc   = iv * gamma[c];
        scale[c] = sc;
        shift[c] = beta[c] - mean*sc;
    }
}

// ---------------- final: BN3+ReLU applied to extremal raw value ----------------
__global__ __launch_bounds__(128) void maxout_kernel(float* __restrict__ out) {
    int q = blockIdx.x;            // b*S+s
    int b = q / SS, s = q % SS;
    int c = threadIdx.x;           // 0..127
    float sc = d_scale3[c], sh = d_shift3[c];
    float v = (sc >= 0.0f) ? d_qmax[(size_t)q*128 + c] : d_qmin[(size_t)q*128 + c];
    out[OUT_FEAT_OFF + ((size_t)b*H3 + c)*SS + s] = fmaxf(fmaf(v, sc, sh), 0.0f);
}

// ---------------- launch ----------------
extern "C" void kernel_launch(void* const* d_in, const int* in_sizes, int n_in,
                              void* d_out, int out_size)
{
    const float* xyz  = (const float*)d_in[0];
    const float* feat = (const float*)d_in[1];
    const float* W1 = (const float*)d_in[2];
    const float* g1 = (const float*)d_in[3];
    const float* b1 = (const float*)d_in[4];
    const float* W2 = (const float*)d_in[5];
    const float* g2 = (const float*)d_in[6];
    const float* b2 = (const float*)d_in[7];
    const float* W3 = (const float*)d_in[8];
    const float* g3 = (const float*)d_in[9];
    const float* b3 = (const float*)d_in[10];
    float* out = (float*)d_out;

    float *p_y1, *p_y2;
    float *p_s1, *p_q1, *p_s2, *p_q2, *p_s3, *p_q3;
    float *p_sc1, *p_sh1, *p_sc2, *p_sh2, *p_sc3, *p_sh3;
    cudaGetSymbolAddress((void**)&p_y1, d_y1);
    cudaGetSymbolAddress((void**)&p_y2, d_y2);
    cudaGetSymbolAddress((void**)&p_s1, d_sum1); cudaGetSymbolAddress((void**)&p_q1, d_sq1);
    cudaGetSymbolAddress((void**)&p_s2, d_sum2); cudaGetSymbolAddress((void**)&p_q2, d_sq2);
    cudaGetSymbolAddress((void**)&p_s3, d_sum3); cudaGetSymbolAddress((void**)&p_q3, d_sq3);
    cudaGetSymbolAddress((void**)&p_sc1, d_scale1); cudaGetSymbolAddress((void**)&p_sh1, d_shift1);
    cudaGetSymbolAddress((void**)&p_sc2, d_scale2); cudaGetSymbolAddress((void**)&p_sh2, d_shift2);
    cudaGetSymbolAddress((void**)&p_sc3, d_scale3); cudaGetSymbolAddress((void**)&p_sh3, d_shift3);

    zero_stats_kernel<<<1, 128>>>();
    fps_kernel<<<BB, 1024>>>(xyz);
    newxyz_kernel<<<(BB*SS + 255)/256, 256>>>(xyz, out);

    dim3 tgrid(NN/32, CC/32, BB);
    transpose_kernel<<<tgrid, dim3(32,32)>>>(feat);

    knn_kernel<<<BB*SS, 128>>>(xyz);

    // layer 1 (gather fused, stats fused)
    mlp_gemm<68, true, false><<<MM/64, 256>>>(nullptr, W1, p_y1, nullptr, nullptr, xyz, p_s1, p_q1);
    finalize_kernel<<<1, 128>>>(H1, p_s1, p_q1, g1, b1, p_sc1, p_sh1);

    // layer 2 (stats fused)
    mlp_gemm<64, false, true><<<MM/64, 256>>>(p_y1, W2, p_y2, p_sc1, p_sh1, nullptr, p_s2, p_q2);
    finalize_kernel<<<1, 128>>>(H2, p_s2, p_q2, g2, b2, p_sc2, p_sh2);

    // layer 3: one query per block, emits qmax/qmin + stats (no y3)
    gemm3_kernel<<<MM/32, 256>>>(p_y2, W3, p_sc2, p_sh2);
    finalize_kernel<<<1, 128>>>(H3, p_s3, p_q3, g3, b3, p_sc3, p_sh3);

    maxout_kernel<<<BB*SS, 128>>>(out);
}

// round 4
// speedup vs baseline: 2.1136x; 1.0461x over previous
#include <cuda_runtime.h>
#include <cuda_bf16.h>
#include <cfloat>
#include <cstdint>

// Problem constants
#define BB 8
#define NN 4096
#define CC 64
#define SS 1024
#define KK 32
#define MM (BB*SS*KK)      // 262144
#define H1 64
#define H2 64
#define H3 128
#define EPSBN 1e-5f

#define OUT_XYZ_OFF 0
#define OUT_FEAT_OFF (BB*SS*3)   // 24576

// ---------------- scratch ----------------
__device__ int   d_fps_idx[BB*SS];
__device__ float d_newxyz[BB*SS*3];
__device__ int   d_gidx[MM];
__device__ float d_featT[BB*NN*CC];          // [b][n][c]
__device__ float d_y1[MM*H1];
__device__ float d_y2[MM*H2];
__device__ float d_qmax[BB*SS*H3];
__device__ float d_qmin[BB*SS*H3];

__device__ float d_sum1[H1],  d_sq1[H1];
__device__ float d_sum2[H2],  d_sq2[H2];
__device__ float d_sum3[H3],  d_sq3[H3];
__device__ float d_scale1[H1], d_shift1[H1];
__device__ float d_scale2[H2], d_shift2[H2];
__device__ float d_scale3[H3], d_shift3[H3];

// exact (non-FMA) squared distance, left-to-right sum
__device__ __forceinline__ float sqdist3(float dx, float dy, float dz) {
    return __fadd_rn(__fadd_rn(__fmul_rn(dx,dx), __fmul_rn(dy,dy)), __fmul_rn(dz,dz));
}

// ---------------- packed f32x2 helpers ----------------
__device__ __forceinline__ unsigned long long pack2(float a) {
    unsigned long long r; unsigned u = __float_as_uint(a);
    asm("mov.b64 %0, {%1, %1};" : "=l"(r) : "r"(u));
    return r;
}
__device__ __forceinline__ unsigned long long fma2(unsigned long long a,
                                                   unsigned long long b,
                                                   unsigned long long c) {
    unsigned long long d;
    asm("fma.rn.f32x2 %0, %1, %2, %3;" : "=l"(d) : "l"(a), "l"(b), "l"(c));
    return d;
}
__device__ __forceinline__ float2 unpack2(unsigned long long v) {
    unsigned lo, hi;
    asm("mov.b64 {%0, %1}, %2;" : "=r"(lo), "=r"(hi) : "l"(v));
    return make_float2(__uint_as_float(lo), __uint_as_float(hi));
}

// ---------------- zero stats ----------------
__global__ void zero_stats_kernel() {
    int t = threadIdx.x;
    if (t < H1) { d_sum1[t]=0.f; d_sq1[t]=0.f; }
    if (t < H2) { d_sum2[t]=0.f; d_sq2[t]=0.f; }
    if (t < H3) { d_sum3[t]=0.f; d_sq3[t]=0.f; }
}

// ---------------- FPS: 1024 threads, 4 pts/thread, redux + single barrier ----------------
__global__ __launch_bounds__(1024) void fps_kernel(const float* __restrict__ xyz) {
    int b = blockIdx.x;
    const float* px = xyz + (size_t)b*NN*3;
    int t = threadIdx.x;
    int lane = t & 31, warp = t >> 5;     // 32 warps

    float X[4], Y[4], Z[4], D[4];
#pragma unroll
    for (int j = 0; j < 4; j++) {
        int p = j*1024 + t;
        X[j] = px[p*3+0]; Y[j] = px[p*3+1]; Z[j] = px[p*3+2];
        D[j] = 1e10f;
    }

    __shared__ unsigned s_v[2][32];
    __shared__ unsigned s_i[2][32];

    int far = 0;
    int par = 0;
    for (int it = 0; it < SS; ++it) {
        if (t == 0) d_fps_idx[b*SS + it] = far;
        float cx = px[far*3+0], cy = px[far*3+1], cz = px[far*3+2];

        float bv = -1.0f; int bi = 0;
#pragma unroll
        for (int j = 0; j < 4; j++) {
            float d = sqdist3(X[j]-cx, Y[j]-cy, Z[j]-cz);
            D[j] = fminf(D[j], d);
            if (D[j] > bv) { bv = D[j]; bi = j*1024 + t; }
        }
        unsigned db   = __float_as_uint(bv);
        unsigned vmax = __reduce_max_sync(0xffffffffu, db);
        unsigned imin = __reduce_min_sync(0xffffffffu, (db == vmax) ? (unsigned)bi : 0xffffffffu);
        if (lane == 0) { s_v[par][warp] = vmax; s_i[par][warp] = imin; }
        __syncthreads();
        unsigned v2 = s_v[par][lane];
        unsigned i2 = s_i[par][lane];
        unsigned vm2 = __reduce_max_sync(0xffffffffu, v2);
        unsigned im2 = __reduce_min_sync(0xffffffffu, (v2 == vm2) ? i2 : 0xffffffffu);
        far = (int)im2;
        par ^= 1;
    }
}

// ---------------- gather new_xyz (also to out) ----------------
__global__ void newxyz_kernel(const float* __restrict__ xyz, float* __restrict__ out) {
    int i = blockIdx.x * blockDim.x + threadIdx.x;   // b*S+s
    if (i >= BB*SS) return;
    int b = i / SS;
    int idx = d_fps_idx[i];
#pragma unroll
    for (int c = 0; c < 3; c++) {
        float v = xyz[((size_t)b*NN + idx)*3 + c];
        d_newxyz[i*3 + c] = v;
        out[OUT_XYZ_OFF + i*3 + c] = v;
    }
}

// ---------------- transpose features [B,C,N] -> [B,N,C] ----------------
__global__ void transpose_kernel(const float* __restrict__ f) {
    __shared__ float tile[32][33];
    int b  = blockIdx.z;
    int c0 = blockIdx.y * 32;
    int n0 = blockIdx.x * 32;
    int tx = threadIdx.x, ty = threadIdx.y;
    tile[ty][tx] = f[(size_t)b*CC*NN + (size_t)(c0+ty)*NN + (n0+tx)];
    __syncthreads();
    d_featT[(size_t)b*NN*CC + (size_t)(n0+ty)*CC + (c0+tx)] = tile[tx][ty];
}

// ---------------- kNN: register-resident, redux, single barrier/round ----------------
__global__ __launch_bounds__(128) void knn_kernel(const float* __restrict__ xyz) {
    int q = blockIdx.x;                 // b*S+s
    int b = q / SS;
    const float* px = xyz + (size_t)b*NN*3;
    int t = threadIdx.x;
    int lane = t & 31, warp = t >> 5;

    float qx = d_newxyz[q*3+0], qy = d_newxyz[q*3+1], qz = d_newxyz[q*3+2];

    float D[32];
#pragma unroll
    for (int i = 0; i < 32; i++) {
        int p = i*128 + t;
        D[i] = sqdist3(px[p*3+0]-qx, px[p*3+1]-qy, px[p*3+2]-qz);
    }
    float bv = FLT_MAX; int bs = 0;
#pragma unroll
    for (int i = 0; i < 32; i++)
        if (D[i] < bv) { bv = D[i]; bs = i; }

    __shared__ unsigned wv[2][4];
    __shared__ unsigned wi[2][4];

    int par = 0;
    for (int kk = 0; kk < KK; ++kk) {
        unsigned db   = __float_as_uint(bv);
        unsigned vmin = __reduce_min_sync(0xffffffffu, db);
        unsigned p    = (unsigned)(bs*128 + t);
        unsigned imin = __reduce_min_sync(0xffffffffu, (db == vmin) ? p : 0xffffffffu);
        if (lane == 0) { wv[par][warp] = vmin; wi[par][warp] = imin; }
        __syncthreads();
        unsigned v2 = (lane < 4) ? wv[par][lane] : 0xffffffffu;
        unsigned i2 = (lane < 4) ? wi[par][lane] : 0xffffffffu;
        unsigned vb = __reduce_min_sync(0xffffffffu, v2);
        unsigned fb = __reduce_min_sync(0xffffffffu, (v2 == vb) ? i2 : 0xffffffffu);
        if (t == 0) d_gidx[q*KK + kk] = (int)fb;
        if ((fb & 127u) == (unsigned)t) {
            D[fb >> 7] = FLT_MAX;
            float nv = FLT_MAX; int ns = 0;
#pragma unroll
            for (int i = 0; i < 32; i++)
                if (D[i] < nv) { nv = D[i]; ns = i; }
            bv = nv; bs = ns;
        }
        par ^= 1;
    }
}

// ---------------- unified MLP GEMM, packed f32x2 ----------------
// EPI=0: store Y[M,64] + fused BN stats (tree reduce)
// EPI=1: per-query (32-row) max/min of raw accs + stats; no Y store. cofs = column offset.
template<int CINK, bool GATHER, bool NORM, int EPI>
__global__ __launch_bounds__(256) void mlp_gemm(
    const float* __restrict__ A, const float* __restrict__ W,
    float* __restrict__ Y, int cofs,
    const float* __restrict__ scale, const float* __restrict__ shift,
    const float* __restrict__ xyz,
    float* __restrict__ gsum, float* __restrict__ gsq)
{
    constexpr int BM = 64;
    constexpr int ASTR = 69;            // odd stride -> conflict-free MMA loads
    constexpr int WSTR = 68;            // 16B-aligned rows
    __shared__ __align__(16) float As[BM*ASTR];
    __shared__ __align__(16) float Ws[CINK*WSTR];

    int tid = threadIdx.x;
    int m0 = blockIdx.x * BM;

    // ---- W load ----
    if (GATHER) {
        for (int i = tid; i < CINK*64; i += 256) {
            int k = i % CINK;        // CINK = 68, col 3 is zero pad
            int c = i / CINK;
            float v = 0.0f;
            if (k != 3) v = W[c*67 + (k < 3 ? k : k-1)];
            Ws[k*WSTR + c] = v;
        }
    } else {
        for (int i = tid; i < CINK*64; i += 256) {
            int k = i % CINK;
            int c = i / CINK;
            Ws[k*WSTR + c] = W[c*CINK + k];
        }
    }

    // ---- A tile ----
    if (GATHER) {
        int warp = tid >> 5, lane = tid & 31;
        for (int r = warp; r < BM; r += 8) {
            int m = m0 + r;
            int b = m >> 15;
            int s = (m >> 5) & (SS-1);
            int idx = d_gidx[m];
            if (lane < 16) {
                const float4* f4 = (const float4*)(d_featT + ((size_t)(b*NN + idx))*CC);
                float4 v = f4[lane];
                float* dst = &As[r*ASTR + 4 + lane*4];
                dst[0] = v.x; dst[1] = v.y; dst[2] = v.z; dst[3] = v.w;
            } else if (lane < 19) {
                int c = lane - 16;
                As[r*ASTR + c] = xyz[((size_t)(b*NN + idx))*3 + c]
                               - d_newxyz[(b*SS + s)*3 + c];
            } else if (lane == 19) {
                As[r*ASTR + 3] = 0.0f;
            }
        }
    } else {
        const float4* A4 = (const float4*)(A + (size_t)m0*CINK);
        for (int i = tid; i < BM*(CINK/4); i += 256) {
            int r  = i >> 4;       // CINK/4 == 16
            int cg = i & 15;
            float4 v = A4[i];
            if (NORM) {
                int c = cg*4;
                v.x = fmaxf(fmaf(v.x, __ldg(&scale[c+0]), __ldg(&shift[c+0])), 0.0f);
                v.y = fmaxf(fmaf(v.y, __ldg(&scale[c+1]), __ldg(&shift[c+1])), 0.0f);
                v.z = fmaxf(fmaf(v.z, __ldg(&scale[c+2]), __ldg(&shift[c+2])), 0.0f);
                v.w = fmaxf(fmaf(v.w, __ldg(&scale[c+3]), __ldg(&shift[c+3])), 0.0f);
            }
            float* dst = &As[r*ASTR + cg*4];
            dst[0] = v.x; dst[1] = v.y; dst[2] = v.z; dst[3] = v.w;
        }
    }
    __syncthreads();

    // ---- MMA: 4 rows x 4 cols per thread, packed pairs ----
    int tx = tid & 15, ty = tid >> 4;
    int r0 = ty*4, c0 = tx*4;
    unsigned long long acc0[4], acc1[4];
#pragma unroll
    for (int i = 0; i < 4; i++) { acc0[i] = 0ull; acc1[i] = 0ull; }

#pragma unroll 4
    for (int k = 0; k < CINK; k++) {
        ulonglong2 w = *(const ulonglong2*)&Ws[k*WSTR + c0];
#pragma unroll
        for (int i = 0; i < 4; i++) {
            unsigned long long a = pack2(As[(r0+i)*ASTR + k]);
            acc0[i] = fma2(a, w.x, acc0[i]);
            acc1[i] = fma2(a, w.y, acc1[i]);
        }
    }

    // unpack
    float accf[4][4];
#pragma unroll
    for (int i = 0; i < 4; i++) {
        float2 p = unpack2(acc0[i]);
        float2 q = unpack2(acc1[i]);
        accf[i][0] = p.x; accf[i][1] = p.y; accf[i][2] = q.x; accf[i][3] = q.y;
    }

    if (EPI == 0) {
#pragma unroll
        for (int i = 0; i < 4; i++) {
            float4 v = make_float4(accf[i][0], accf[i][1], accf[i][2], accf[i][3]);
            *(float4*)&Y[(size_t)(m0 + r0 + i)*64 + c0] = v;
        }
        float ls[4], lq[4];
#pragma unroll
        for (int j = 0; j < 4; j++) {
            ls[j] = 0.f; lq[j] = 0.f;
#pragma unroll
            for (int i = 0; i < 4; i++) { float v = accf[i][j]; ls[j] += v; lq[j] += v*v; }
        }
        __syncthreads();                 // As no longer needed -> reuse as reduction buffer
        float2* red = (float2*)As;       // [16][64]
#pragma unroll
        for (int j = 0; j < 4; j++)
            red[ty*64 + c0 + j] = make_float2(ls[j], lq[j]);
        __syncthreads();
        if (tid < 64) {
            float s = 0.f, s2 = 0.f;
#pragma unroll
            for (int t = 0; t < 16; t++) { float2 v = red[t*64 + tid]; s += v.x; s2 += v.y; }
            atomicAdd(&gsum[tid], s);
            atomicAdd(&gsq [tid], s2);
        }
    } else {
        // per-thread partials (4 rows within one query half)
        float ls[4], lq[4], mx[4], mn[4];
#pragma unroll
        for (int j = 0; j < 4; j++) {
            float v0 = accf[0][j];
            ls[j] = 0.f; lq[j] = 0.f; mx[j] = v0; mn[j] = v0;
#pragma unroll
            for (int i = 0; i < 4; i++) {
                float v = accf[i][j];
                ls[j] += v; lq[j] += v*v;
                mx[j] = fmaxf(mx[j], v); mn[j] = fminf(mn[j], v);
            }
        }
        __syncthreads();
        float2* red2 = (float2*)As;                 // [16][64] sum/sq : 8KB
        float*  rmx  = (float*)(red2 + 1024);       // [16][64] : 4KB
        float*  rmn  = rmx + 1024;                  // [16][64] : 4KB
#pragma unroll
        for (int j = 0; j < 4; j++) {
            red2[ty*64 + c0 + j] = make_float2(ls[j], lq[j]);
            rmx [ty*64 + c0 + j] = mx[j];
            rmn [ty*64 + c0 + j] = mn[j];
        }
        __syncthreads();
        if (tid < 128) {
            int qq = tid >> 6, c = tid & 63;
            float M = -FLT_MAX, m = FLT_MAX;
#pragma unroll
            for (int t = 0; t < 8; t++) {
                M = fmaxf(M, rmx[(qq*8 + t)*64 + c]);
                m = fminf(m, rmn[(qq*8 + t)*64 + c]);
            }
            size_t qg = (size_t)blockIdx.x*2 + qq;
            d_qmax[qg*128 + cofs + c] = M;
            d_qmin[qg*128 + cofs + c] = m;
        }
        if (tid < 64) {
            float s = 0.f, s2 = 0.f;
#pragma unroll
            for (int t = 0; t < 16; t++) { float2 v = red2[t*64 + tid]; s += v.x; s2 += v.y; }
            atomicAdd(&gsum[cofs + tid], s);
            atomicAdd(&gsq [cofs + tid], s2);
        }
    }
}

// ---------------- fold BN stats into scale/shift ----------------
__global__ void finalize_kernel(int Cn, const float* __restrict__ sum, const float* __restrict__ sq,
                                const float* __restrict__ gamma, const float* __restrict__ beta,
                                float* __restrict__ scale, float* __restrict__ shift)
{
    int c = threadIdx.x;
    if (c < Cn) {
        const float invM = 1.0f / (float)MM;
        float mean = sum[c] * invM;
        float var  = sq[c] * invM - mean*mean;
        float iv   = rsqrtf(var + EPSBN);
        float sc   = iv * gamma[c];
        scale[c] = sc;
        shift[c] = beta[c] - mean*sc;
    }
}

// ---------------- final: BN3+ReLU applied to extremal raw value ----------------
__global__ __launch_bounds__(128) void maxout_kernel(float* __restrict__ out) {
    int q = blockIdx.x;            // b*S+s
    int b = q / SS, s = q % SS;
    int c = threadIdx.x;           // 0..127
    float sc = d_scale3[c], sh = d_shift3[c];
    float v = (sc >= 0.0f) ? d_qmax[(size_t)q*128 + c] : d_qmin[(size_t)q*128 + c];
    out[OUT_FEAT_OFF + ((size_t)b*H3 + c)*SS + s] = fmaxf(fmaf(v, sc, sh), 0.0f);
}

// ---------------- launch ----------------
extern "C" void kernel_launch(void* const* d_in, const int* in_sizes, int n_in,
                              void* d_out, int out_size)
{
    const float* xyz  = (const float*)d_in[0];
    const float* feat = (const float*)d_in[1];
    const float* W1 = (const float*)d_in[2];
    const float* g1 = (const float*)d_in[3];
    const float* b1 = (const float*)d_in[4];
    const float* W2 = (const float*)d_in[5];
    const float* g2 = (const float*)d_in[6];
    const float* b2 = (const float*)d_in[7];
    const float* W3 = (const float*)d_in[8];
    const float* g3 = (const float*)d_in[9];
    const float* b3 = (const float*)d_in[10];
    float* out = (float*)d_out;

    float *p_y1, *p_y2;
    float *p_s1, *p_q1, *p_s2, *p_q2, *p_s3, *p_q3;
    float *p_sc1, *p_sh1, *p_sc2, *p_sh2, *p_sc3, *p_sh3;
    cudaGetSymbolAddress((void**)&p_y1, d_y1);
    cudaGetSymbolAddress((void**)&p_y2, d_y2);
    cudaGetSymbolAddress((void**)&p_s1, d_sum1); cudaGetSymbolAddress((void**)&p_q1, d_sq1);
    cudaGetSymbolAddress((void**)&p_s2, d_sum2); cudaGetSymbolAddress((void**)&p_q2, d_sq2);
    cudaGetSymbolAddress((void**)&p_s3, d_sum3); cudaGetSymbolAddress((void**)&p_q3, d_sq3);
    cudaGetSymbolAddress((void**)&p_sc1, d_scale1); cudaGetSymbolAddress((void**)&p_sh1, d_shift1);
    cudaGetSymbolAddress((void**)&p_sc2, d_scale2); cudaGetSymbolAddress((void**)&p_sh2, d_shift2);
    cudaGetSymbolAddress((void**)&p_sc3, d_scale3); cudaGetSymbolAddress((void**)&p_sh3, d_shift3);

    zero_stats_kernel<<<1, 128>>>();
    fps_kernel<<<BB, 1024>>>(xyz);
    newxyz_kernel<<<(BB*SS + 255)/256, 256>>>(xyz, out);

    dim3 tgrid(NN/32, CC/32, BB);
    transpose_kernel<<<tgrid, dim3(32,32)>>>(feat);

    knn_kernel<<<BB*SS, 128>>>(xyz);

    // layer 1 (gather fused, stats fused)
    mlp_gemm<68, true, false, 0><<<MM/64, 256>>>(nullptr, W1, p_y1, 0, nullptr, nullptr, xyz, p_s1, p_q1);
    finalize_kernel<<<1, 128>>>(H1, p_s1, p_q1, g1, b1, p_sc1, p_sh1);

    // layer 2 (stats fused)
    mlp_gemm<64, false, true, 0><<<MM/64, 256>>>(p_y1, W2, p_y2, 0, p_sc1, p_sh1, nullptr, p_s2, p_q2);
    finalize_kernel<<<1, 128>>>(H2, p_s2, p_q2, g2, b2, p_sc2, p_sh2);

    // layer 3: two column-half launches, 2 queries/block, qmax/qmin + stats, no Y
    mlp_gemm<64, false, true, 1><<<MM/64, 256>>>(p_y2, W3,         nullptr, 0,  p_sc2, p_sh2, nullptr, p_s3, p_q3);
    mlp_gemm<64, false, true, 1><<<MM/64, 256>>>(p_y2, W3 + 64*64, nullptr, 64, p_sc2, p_sh2, nullptr, p_s3, p_q3);
    finalize_kernel<<<1, 128>>>(H3, p_s3, p_q3, g3, b3, p_sc3, p_sh3);

    maxout_kernel<<<BB*SS, 128>>>(out);
}